// round 13
// baseline (speedup 1.0000x reference)
#include <cuda_runtime.h>
#include <cuda_bf16.h>
#include <cstdint>

typedef unsigned int u32;

#define NB 64
#define CC 512
#define LL 256
#define EPSF 1e-12f
#define NT 8                    // 64-wide tiles for huber
#define NPAIR (NT*(NT+1)/2)     // 36
#define NT2 4                   // 128-wide tiles for dist
#define NPAIR2 (NT2*(NT2+1)/2)  // 10
#define SW 40                   // smem bf16 row stride (conflict-free ldmatrix)

// -------- scratch (static device globals: allocation-free rule) ----------
__device__ float g_sq_s[NB*CC];
__device__ float g_sq_t[NB*CC];
__device__ int   g_idx[NB*CC];
__device__ int   g_npos[NB];
__device__ float g_sum_s[NB];
__device__ float g_sum_t[NB];
__device__ float g_Ds[NB*CC*CC];
__device__ float g_Dt[NB*CC*CC];
// compacted bf16 hi/lo copies (row r = compacted positive row r)
__device__ __nv_bfloat16 g_hs[NB*CC*LL];
__device__ __nv_bfloat16 g_ls[NB*CC*LL];
__device__ __nv_bfloat16 g_ht[NB*CC*LL];
__device__ __nv_bfloat16 g_lt[NB*CC*LL];

// =================== kernel 0: index lists + init (tiny) ==================
__global__ void k_index(const int* __restrict__ targ, float* __restrict__ out) {
    int n    = blockIdx.x;
    int tid  = threadIdx.x;           // 512
    int lane = tid & 31;
    int wid  = tid >> 5;
    __shared__ int sh_wsum[16];

    int m = (targ[n*CC + tid] != 0);
    unsigned bal = __ballot_sync(0xffffffffu, m);
    int wpre = __popc(bal & ((1u << lane) - 1u));
    if (lane == 0) sh_wsum[wid] = __popc(bal);
    __syncthreads();
    if (tid == 0) {
        int acc = 0;
        #pragma unroll
        for (int w = 0; w < 16; w++) { int v = sh_wsum[w]; sh_wsum[w] = acc; acc += v; }
        g_npos[n]  = acc;
        g_sum_s[n] = 0.f;
        g_sum_t[n] = 0.f;
        if (n == 0) out[0] = 0.f;
    }
    __syncthreads();
    if (m) g_idx[n*CC + sh_wsum[wid] + wpre] = tid;
}

// ---- pack helper: float4 -> (hi uint2, lo uint2) bf16 pairs --------------
__device__ __forceinline__ void pack4(float4 v, uint2& ho, uint2& lo) {
    __nv_bfloat16 h0 = __float2bfloat16(v.x);
    __nv_bfloat16 h1 = __float2bfloat16(v.y);
    __nv_bfloat16 h2 = __float2bfloat16(v.z);
    __nv_bfloat16 h3 = __float2bfloat16(v.w);
    __nv_bfloat16 l0 = __float2bfloat16(v.x - __bfloat162float(h0));
    __nv_bfloat16 l1 = __float2bfloat16(v.y - __bfloat162float(h1));
    __nv_bfloat16 l2 = __float2bfloat16(v.z - __bfloat162float(h2));
    __nv_bfloat16 l3 = __float2bfloat16(v.w - __bfloat162float(h3));
    __nv_bfloat162 hp0 = __halves2bfloat162(h0, h1);
    __nv_bfloat162 hp1 = __halves2bfloat162(h2, h3);
    __nv_bfloat162 lp0 = __halves2bfloat162(l0, l1);
    __nv_bfloat162 lp1 = __halves2bfloat162(l2, l3);
    ho.x = *(u32*)&hp0; ho.y = *(u32*)&hp1;
    lo.x = *(u32*)&lp0; lo.y = *(u32*)&lp1;
}

// ====== kernel 1: gather + norms + hi/lo bf16 split to gmem (merged) ======
// grid (NB, 16), block 256 = 8 warps; one warp per compacted row, strided
__global__ void k_prep(const float* __restrict__ s, const float* __restrict__ t) {
    int n    = blockIdx.x;
    int P    = g_npos[n];
    int tid  = threadIdx.x;
    int lane = tid & 31;
    int wid  = tid >> 5;
    int gw   = blockIdx.y * 8 + wid;  // 0..127

    const float* sb = s + (long long)n*CC*LL;
    const float* tb = t + (long long)n*CC*LL;
    long long obase = (long long)n*CC*LL;

    for (int r = gw; r < P; r += 128) {
        int src = g_idx[n*CC + r];
        const float4* rs = (const float4*)(sb + src*LL);
        const float4* rt = (const float4*)(tb + src*LL);
        float a = 0.f, b = 0.f;
        #pragma unroll
        for (int c = 0; c < 2; c++) {
            int e = lane + c*32;      // float4 index 0..63
            float4 v = rs[e];
            a += v.x*v.x + v.y*v.y + v.z*v.z + v.w*v.w;
            uint2 ho, lo;
            pack4(v, ho, lo);
            ((uint2*)(g_hs + obase + r*LL))[e] = ho;
            ((uint2*)(g_ls + obase + r*LL))[e] = lo;
            float4 w = rt[e];
            b += w.x*w.x + w.y*w.y + w.z*w.z + w.w*w.w;
            pack4(w, ho, lo);
            ((uint2*)(g_ht + obase + r*LL))[e] = ho;
            ((uint2*)(g_lt + obase + r*LL))[e] = lo;
        }
        #pragma unroll
        for (int off = 16; off; off >>= 1) {
            a += __shfl_down_sync(0xffffffffu, a, off);
            b += __shfl_down_sync(0xffffffffu, b, off);
        }
        if (lane == 0) { g_sq_s[n*CC + r] = a; g_sq_t[n*CC + r] = b; }
    }
}

// ----------------------- mma helpers --------------------------------------
__device__ __forceinline__ void ldsm_x4(u32 (&r)[4], u32 addr) {
    asm volatile("ldmatrix.sync.aligned.m8n8.x4.shared.b16 {%0,%1,%2,%3}, [%4];"
        : "=r"(r[0]), "=r"(r[1]), "=r"(r[2]), "=r"(r[3]) : "r"(addr));
}

__device__ __forceinline__ void mma16816(float (&c)[4], const u32 (&a)[4],
                                         u32 b0, u32 b1) {
    asm volatile(
        "mma.sync.aligned.m16n8k16.row.col.f32.bf16.bf16.f32 "
        "{%0,%1,%2,%3},{%4,%5,%6,%7},{%8,%9},{%0,%1,%2,%3};"
        : "+f"(c[0]), "+f"(c[1]), "+f"(c[2]), "+f"(c[3])
        : "r"(a[0]), "r"(a[1]), "r"(a[2]), "r"(a[3]), "r"(b0), "r"(b1));
}

// copy 16 bf16 (32 B) from gmem (or zeros) to smem
__device__ __forceinline__ void cp32(const __nv_bfloat16* __restrict__ src,
                                     bool valid, __nv_bfloat16* dst) {
    uint4 v0, v1;
    if (valid) {
        v0 = ((const uint4*)src)[0];
        v1 = ((const uint4*)src)[1];
    } else {
        v0 = make_uint4(0,0,0,0);
        v1 = make_uint4(0,0,0,0);
    }
    ((uint4*)dst)[0] = v0;
    ((uint4*)dst)[1] = v1;
}

// ============ kernel 2: Gram -> distances via bf16-split HMMA =============
// 256 thr, 128x128 tile, warps 4(m)x2(n) each 32x64, K-chunk 32.
// dot = Ah*Bh + Ah*Bl + Al*Bh  (2-term bf16 split, ~fp32 precision)
// Reads pre-split compacted bf16 rows directly (no gather, no convert).
__global__ void __launch_bounds__(256, 2) k_dist() {
    int n     = blockIdx.z;
    int which = blockIdx.y;

    const __nv_bfloat16* GH = (which ? g_ht : g_hs) + (long long)n*CC*LL;
    const __nv_bfloat16* GL = (which ? g_lt : g_ls) + (long long)n*CC*LL;
    const float* SQ = which ? (g_sq_t + n*CC)               : (g_sq_s + n*CC);
    float*       D  = which ? (g_Dt   + (long long)n*CC*CC) : (g_Ds   + (long long)n*CC*CC);
    float*       SM = which ? (g_sum_t + n)                 : (g_sum_s + n);

    int P = g_npos[n];

    int tlin = blockIdx.x, bi = 0, rem = NT2;
    while (tlin >= rem) { tlin -= rem; bi++; rem--; }
    int bj = bi + tlin;
    int i0 = bi * 128, j0 = bj * 128;
    if (i0 >= P || j0 >= P) return;
    bool diag = (bi == bj);

    __shared__ __align__(16) __nv_bfloat16 Ah[128*SW];
    __shared__ __align__(16) __nv_bfloat16 Al[128*SW];
    __shared__ __align__(16) __nv_bfloat16 Bhs[128*SW];
    __shared__ __align__(16) __nv_bfloat16 Bls[128*SW];
    __shared__ float red[256];

    int tid  = threadIdx.x;
    int lane = tid & 31;
    int wid  = tid >> 5;
    int wm   = wid & 3;
    int wn   = wid >> 2;              // warp tile origin: (wm*32, wn*64)

    u32 ah = (u32)__cvta_generic_to_shared(Ah);
    u32 al = (u32)__cvta_generic_to_shared(Al);
    u32 bh = diag ? ah : (u32)__cvta_generic_to_shared(Bhs);
    u32 bl = diag ? al : (u32)__cvta_generic_to_shared(Bls);

    float acc[2][8][4];
    #pragma unroll
    for (int mt = 0; mt < 2; mt++) {
        #pragma unroll
        for (int nt = 0; nt < 8; nt++) {
            #pragma unroll
            for (int e = 0; e < 4; e++) acc[mt][nt][e] = 0.f;
        }
    }

    int lrow = tid >> 1;              // loader row 0..127
    int kb   = (tid & 1) * 16;        // loader k-offset 0/16

    bool vA = (i0 + lrow) < P;
    bool vB = (j0 + lrow) < P;
    long long rA = (long long)(i0 + lrow) * LL;
    long long rB = (long long)(j0 + lrow) * LL;

    u32 a_r = (lane & 7) + ((lane >> 3) & 1) * 8;
    u32 a_k = (lane >> 4) * 8;
    u32 b_r = (lane & 7) + (lane >> 4) * 8;
    u32 b_k = ((lane >> 3) & 1) * 8;

    for (int k0 = 0; k0 < LL; k0 += 32) {
        cp32(GH + rA + k0 + kb, vA, &Ah[lrow*SW + kb]);
        cp32(GL + rA + k0 + kb, vA, &Al[lrow*SW + kb]);
        if (!diag) {
            cp32(GH + rB + k0 + kb, vB, &Bhs[lrow*SW + kb]);
            cp32(GL + rB + k0 + kb, vB, &Bls[lrow*SW + kb]);
        }
        __syncthreads();

        #pragma unroll
        for (int ks = 0; ks < 32; ks += 16) {
            #pragma unroll
            for (int pass = 0; pass < 3; pass++) {
                u32 abase = (pass < 2)  ? ah : al;
                u32 bbase = (pass == 1) ? bl : bh;
                u32 afrag[2][4];
                #pragma unroll
                for (int mt = 0; mt < 2; mt++) {
                    u32 arow = wm*32 + mt*16 + a_r;
                    ldsm_x4(afrag[mt], abase + (arow*SW + ks + a_k)*2);
                }
                #pragma unroll
                for (int ng = 0; ng < 4; ng++) {
                    u32 brow = wn*64 + ng*16 + b_r;
                    u32 bfrag[4];
                    ldsm_x4(bfrag, bbase + (brow*SW + ks + b_k)*2);
                    #pragma unroll
                    for (int mt = 0; mt < 2; mt++) {
                        mma16816(acc[mt][ng*2+0], afrag[mt], bfrag[0], bfrag[1]);
                        mma16816(acc[mt][ng*2+1], afrag[mt], bfrag[2], bfrag[3]);
                    }
                }
            }
        }
        __syncthreads();
    }

    // ---- epilogue: distances, store, partial sum ----
    float lsum = 0.f;
    #pragma unroll
    for (int mt = 0; mt < 2; mt++) {
        #pragma unroll
        for (int half = 0; half < 2; half++) {
            int i = i0 + wm*32 + mt*16 + (lane >> 2) + half*8;
            if (i < P) {
                float sqi = SQ[i];
                #pragma unroll
                for (int nt = 0; nt < 8; nt++) {
                    #pragma unroll
                    for (int e = 0; e < 2; e++) {
                        int j = j0 + wn*64 + nt*8 + (lane & 3)*2 + e;
                        if (j < P) {
                            float d;
                            if (i == j) {
                                d = 0.f;
                            } else {
                                float d2 = sqi + SQ[j] - 2.f * acc[mt][nt][half*2 + e];
                                d2 = fmaxf(d2, EPSF);
                                d  = d2 * rsqrtf(d2);
                            }
                            D[i*CC + j] = d;
                            lsum += d;
                        }
                    }
                }
            }
        }
    }

    red[tid] = lsum;
    __syncthreads();
    #pragma unroll
    for (int s2 = 128; s2; s2 >>= 1) {
        if (tid < s2) red[tid] += red[tid + s2];
        __syncthreads();
    }
    if (tid == 0) {
        float w = diag ? 1.f : 2.f;
        atomicAdd(SM, red[0] * w);
    }
}

// ==================== kernel 3: Huber sum (64-tiles) ======================
__global__ void k_huber(float* __restrict__ out) {
    int n   = blockIdx.x;
    int tid = threadIdx.x;
    int P = g_npos[n];
    if (P <= 1) return;

    int tlin = blockIdx.y, bi = 0, rem = NT;
    while (tlin >= rem) { tlin -= rem; bi++; rem--; }
    int bj = bi + tlin;
    int i0 = bi * 64, j0 = bj * 64;
    if (i0 >= P || j0 >= P) return;

    float cnt = (float)P * (float)(P - 1);
    float ims = cnt / g_sum_s[n];
    float imt = cnt / g_sum_t[n];

    const float* Ds = g_Ds + (long long)n*CC*CC;
    const float* Dt = g_Dt + (long long)n*CC*CC;

    float lsum = 0.f;
    #pragma unroll
    for (int q = 0; q < 4; q++) {
        int f = tid + 256*q;          // 0..1023 float4 slots
        int i = i0 + (f >> 4);
        int j = j0 + (f & 15) * 4;
        if (i < P) {
            float4 ds4 = *(const float4*)(Ds + i*CC + j);
            float4 dt4 = *(const float4*)(Dt + i*CC + j);
            float dsv[4] = {ds4.x, ds4.y, ds4.z, ds4.w};
            float dtv[4] = {dt4.x, dt4.y, dt4.z, dt4.w};
            #pragma unroll
            for (int e = 0; e < 4; e++) {
                if (j + e < P) {
                    float diff = dsv[e]*ims - dtv[e]*imt;
                    float ad = fabsf(diff);
                    lsum += (ad < 1.f) ? 0.5f*diff*diff : ad - 0.5f;
                }
            }
        }
    }

    __shared__ float red[256];
    red[tid] = lsum;
    __syncthreads();
    #pragma unroll
    for (int s2 = 128; s2; s2 >>= 1) {
        if (tid < s2) red[tid] += red[tid + s2];
        __syncthreads();
    }
    if (tid == 0) {
        float w = (bi == bj) ? 1.f : 2.f;
        atomicAdd(out, red[0] * w / (float)P);
    }
}

// ============================== launcher =================================
extern "C" void kernel_launch(void* const* d_in, const int* in_sizes, int n_in,
                              void* d_out, int out_size) {
    const float* s    = (const float*)d_in[0];
    const float* t    = (const float*)d_in[1];
    const int*   targ = (const int*)d_in[2];
    float* out = (float*)d_out;

    k_index<<<NB, 512>>>(targ, out);
    dim3 g1(NB, 16);
    k_prep<<<g1, 256>>>(s, t);
    dim3 g2(NPAIR2, 2, NB);
    k_dist<<<g2, 256>>>();
    dim3 g3(NB, NPAIR);
    k_huber<<<g3, 256>>>(out);
}

// round 15
// speedup vs baseline: 1.0458x; 1.0458x over previous
#include <cuda_runtime.h>
#include <cuda_bf16.h>
#include <cuda_fp16.h>
#include <cstdint>

typedef unsigned int u32;

#define NB 64
#define CC 512
#define LL 256
#define EPSF 1e-12f
#define NT 8                    // 64-wide tiles for huber
#define NPAIR (NT*(NT+1)/2)     // 36
#define NT2 4                   // 128-wide tiles for dist
#define NPAIR2 (NT2*(NT2+1)/2)  // 10
#define SW 40                   // smem bf16 row stride (conflict-free ldmatrix)

// -------- scratch (static device globals: allocation-free rule) ----------
__device__ float  g_sq_s[NB*CC];
__device__ float  g_sq_t[NB*CC];
__device__ int    g_idx[NB*CC];
__device__ int    g_npos[NB];
__device__ float  g_sum_s[NB];
__device__ float  g_sum_t[NB];
__device__ __half g_Ds[NB*CC*CC];    // fp16 distance matrices (upper tiles)
__device__ __half g_Dt[NB*CC*CC];

// =================== kernel 0: index lists + init (tiny) ==================
__global__ void k_index(const int* __restrict__ targ, float* __restrict__ out) {
    int n    = blockIdx.x;
    int tid  = threadIdx.x;           // 512
    int lane = tid & 31;
    int wid  = tid >> 5;
    __shared__ int sh_wsum[16];

    int m = (targ[n*CC + tid] != 0);
    unsigned bal = __ballot_sync(0xffffffffu, m);
    int wpre = __popc(bal & ((1u << lane) - 1u));
    if (lane == 0) sh_wsum[wid] = __popc(bal);
    __syncthreads();
    if (tid == 0) {
        int acc = 0;
        #pragma unroll
        for (int w = 0; w < 16; w++) { int v = sh_wsum[w]; sh_wsum[w] = acc; acc += v; }
        g_npos[n]  = acc;
        g_sum_s[n] = 0.f;
        g_sum_t[n] = 0.f;
        if (n == 0) out[0] = 0.f;
    }
    __syncthreads();
    if (m) g_idx[n*CC + sh_wsum[wid] + wpre] = tid;
}

// ============ kernel 1: row norms via gather (no copy) ====================
__global__ void k_norm(const float* __restrict__ s, const float* __restrict__ t) {
    int n    = blockIdx.x;
    int P    = g_npos[n];
    int tid  = threadIdx.x;
    int lane = tid & 31;
    int wid  = tid >> 5;
    int gw   = blockIdx.y * 8 + wid;

    const float* sb = s + (long long)n*CC*LL;
    const float* tb = t + (long long)n*CC*LL;

    for (int r = gw; r < P; r += 128) {
        int src = g_idx[n*CC + r];
        const float4* rs = (const float4*)(sb + src*LL);
        const float4* rt = (const float4*)(tb + src*LL);
        float a = 0.f, b = 0.f;
        #pragma unroll
        for (int c = 0; c < 2; c++) {
            int e = lane + c*32;
            float4 v = rs[e];
            a += v.x*v.x + v.y*v.y + v.z*v.z + v.w*v.w;
            float4 w = rt[e];
            b += w.x*w.x + w.y*w.y + w.z*w.z + w.w*w.w;
        }
        #pragma unroll
        for (int off = 16; off; off >>= 1) {
            a += __shfl_down_sync(0xffffffffu, a, off);
            b += __shfl_down_sync(0xffffffffu, b, off);
        }
        if (lane == 0) { g_sq_s[n*CC + r] = a; g_sq_t[n*CC + r] = b; }
    }
}

// ----------------------- helpers -----------------------------------------
__device__ __forceinline__ void ldsm_x4(u32 (&r)[4], u32 addr) {
    asm volatile("ldmatrix.sync.aligned.m8n8.x4.shared.b16 {%0,%1,%2,%3}, [%4];"
        : "=r"(r[0]), "=r"(r[1]), "=r"(r[2]), "=r"(r[3]) : "r"(addr));
}

__device__ __forceinline__ void mma16816(float (&c)[4], const u32 (&a)[4],
                                         u32 b0, u32 b1) {
    asm volatile(
        "mma.sync.aligned.m16n8k16.row.col.f32.bf16.bf16.f32 "
        "{%0,%1,%2,%3},{%4,%5,%6,%7},{%8,%9},{%0,%1,%2,%3};"
        : "+f"(c[0]), "+f"(c[1]), "+f"(c[2]), "+f"(c[3])
        : "r"(a[0]), "r"(a[1]), "r"(a[2]), "r"(a[3]), "r"(b0), "r"(b1));
}

// load 4 float4 (16 floats) from gmem, or zeros
__device__ __forceinline__ void ld16(const float* __restrict__ p, bool valid,
                                     float4 (&buf)[4]) {
    if (valid) {
        #pragma unroll
        for (int q = 0; q < 4; q++) buf[q] = ((const float4*)p)[q];
    } else {
        #pragma unroll
        for (int q = 0; q < 4; q++) buf[q] = make_float4(0,0,0,0);
    }
}

// split 16 floats (in regs) into hi/lo bf16 and store to smem
__device__ __forceinline__ void st16(const float4 (&buf)[4],
                                     __nv_bfloat16* hdst, __nv_bfloat16* ldst) {
    float v[16];
    #pragma unroll
    for (int q = 0; q < 4; q++) {
        v[4*q+0] = buf[q].x; v[4*q+1] = buf[q].y;
        v[4*q+2] = buf[q].z; v[4*q+3] = buf[q].w;
    }
    u32 hw[8], lw[8];
    #pragma unroll
    for (int q = 0; q < 8; q++) {
        float x0 = v[2*q], x1 = v[2*q+1];
        __nv_bfloat16 h0 = __float2bfloat16(x0);
        __nv_bfloat16 h1 = __float2bfloat16(x1);
        float r0 = x0 - __bfloat162float(h0);
        float r1 = x1 - __bfloat162float(h1);
        __nv_bfloat162 hp = __halves2bfloat162(h0, h1);
        __nv_bfloat162 lp = __halves2bfloat162(__float2bfloat16(r0), __float2bfloat16(r1));
        hw[q] = *(u32*)&hp;
        lw[q] = *(u32*)&lp;
    }
    ((uint4*)hdst)[0] = make_uint4(hw[0], hw[1], hw[2], hw[3]);
    ((uint4*)hdst)[1] = make_uint4(hw[4], hw[5], hw[6], hw[7]);
    ((uint4*)ldst)[0] = make_uint4(lw[0], lw[1], lw[2], lw[3]);
    ((uint4*)ldst)[1] = make_uint4(lw[4], lw[5], lw[6], lw[7]);
}

// ============ kernel 2: Gram -> distances via bf16-split HMMA =============
// 256 thr, 128x128 tile, warps 4(m)x2(n) each 32x64, K-chunk 32,
// register double-buffered fp32 loads. dot = Ah*Bh + Ah*Bl + Al*Bh.
__global__ void __launch_bounds__(256, 2) k_dist(const float* __restrict__ s,
                                                 const float* __restrict__ t) {
    int n     = blockIdx.z;
    int which = blockIdx.y;

    const float* E  = (which ? t : s) + (long long)n*CC*LL;
    const float* SQ = which ? (g_sq_t + n*CC)               : (g_sq_s + n*CC);
    __half*      D  = which ? (g_Dt   + (long long)n*CC*CC) : (g_Ds   + (long long)n*CC*CC);
    float*       SM = which ? (g_sum_t + n)                 : (g_sum_s + n);

    int P = g_npos[n];

    int tlin = blockIdx.x, bi = 0, rem = NT2;
    while (tlin >= rem) { tlin -= rem; bi++; rem--; }
    int bj = bi + tlin;
    int i0 = bi * 128, j0 = bj * 128;
    if (i0 >= P || j0 >= P) return;
    bool diag = (bi == bj);

    __shared__ __align__(16) __nv_bfloat16 Ah[128*SW];
    __shared__ __align__(16) __nv_bfloat16 Al[128*SW];
    __shared__ __align__(16) __nv_bfloat16 Bhs[128*SW];
    __shared__ __align__(16) __nv_bfloat16 Bls[128*SW];
    __shared__ int sIA[128];
    __shared__ int sIB[128];
    __shared__ float red[256];

    int tid  = threadIdx.x;
    int lane = tid & 31;
    int wid  = tid >> 5;
    int wm   = wid & 3;
    int wn   = wid >> 2;              // warp tile origin: (wm*32, wn*64)

    if (tid < 128) {
        int gi = i0 + tid;
        sIA[tid] = (gi < P) ? g_idx[n*CC + gi] : -1;
        int gj = j0 + tid;
        sIB[tid] = (gj < P) ? g_idx[n*CC + gj] : -1;
    }

    u32 ah = (u32)__cvta_generic_to_shared(Ah);
    u32 al = (u32)__cvta_generic_to_shared(Al);
    u32 bh = diag ? ah : (u32)__cvta_generic_to_shared(Bhs);
    u32 bl = diag ? al : (u32)__cvta_generic_to_shared(Bls);

    float acc[2][8][4];
    #pragma unroll
    for (int mt = 0; mt < 2; mt++) {
        #pragma unroll
        for (int nt = 0; nt < 8; nt++) {
            #pragma unroll
            for (int e = 0; e < 4; e++) acc[mt][nt][e] = 0.f;
        }
    }

    int lrow = tid >> 1;              // loader row 0..127
    int kb   = (tid & 1) * 16;        // loader k-offset 0/16

    u32 a_r = (lane & 7) + ((lane >> 3) & 1) * 8;
    u32 a_k = (lane >> 4) * 8;
    u32 b_r = (lane & 7) + (lane >> 4) * 8;
    u32 b_k = ((lane >> 3) & 1) * 8;

    __syncthreads();
    int srcA = sIA[lrow];
    int srcB = sIB[lrow];
    const float* pA = E + srcA*LL + kb;
    const float* pB = E + srcB*LL + kb;

    float4 bufA[4], bufB[4];
    ld16(pA, srcA >= 0, bufA);
    if (!diag) ld16(pB, srcB >= 0, bufB);

    for (int k0 = 0; k0 < LL; k0 += 32) {
        st16(bufA, &Ah[lrow*SW + kb], &Al[lrow*SW + kb]);
        if (!diag) st16(bufB, &Bhs[lrow*SW + kb], &Bls[lrow*SW + kb]);
        __syncthreads();

        if (k0 + 32 < LL) {           // prefetch next chunk during MMA
            ld16(pA + k0 + 32, srcA >= 0, bufA);
            if (!diag) ld16(pB + k0 + 32, srcB >= 0, bufB);
        }

        #pragma unroll
        for (int ks = 0; ks < 32; ks += 16) {
            #pragma unroll
            for (int pass = 0; pass < 3; pass++) {
                u32 abase = (pass < 2)  ? ah : al;
                u32 bbase = (pass == 1) ? bl : bh;
                u32 afrag[2][4];
                #pragma unroll
                for (int mt = 0; mt < 2; mt++) {
                    u32 arow = wm*32 + mt*16 + a_r;
                    ldsm_x4(afrag[mt], abase + (arow*SW + ks + a_k)*2);
                }
                #pragma unroll
                for (int ng = 0; ng < 4; ng++) {
                    u32 brow = wn*64 + ng*16 + b_r;
                    u32 bfrag[4];
                    ldsm_x4(bfrag, bbase + (brow*SW + ks + b_k)*2);
                    #pragma unroll
                    for (int mt = 0; mt < 2; mt++) {
                        mma16816(acc[mt][ng*2+0], afrag[mt], bfrag[0], bfrag[1]);
                        mma16816(acc[mt][ng*2+1], afrag[mt], bfrag[2], bfrag[3]);
                    }
                }
            }
        }
        __syncthreads();
    }

    // ---- epilogue: distances (fp16 pairs), partial sum ----
    float lsum = 0.f;
    #pragma unroll
    for (int mt = 0; mt < 2; mt++) {
        #pragma unroll
        for (int half = 0; half < 2; half++) {
            int i = i0 + wm*32 + mt*16 + (lane >> 2) + half*8;
            if (i < P) {
                float sqi = SQ[i];
                #pragma unroll
                for (int nt = 0; nt < 8; nt++) {
                    int j = j0 + wn*64 + nt*8 + (lane & 3)*2;
                    if (j < P) {
                        float d0 = 0.f, d1 = 0.f;
                        if (i != j) {
                            float d2 = sqi + SQ[j] - 2.f * acc[mt][nt][half*2 + 0];
                            d2 = fmaxf(d2, EPSF);
                            d0 = d2 * rsqrtf(d2);
                        }
                        if (j + 1 < P && i != j + 1) {
                            float d2 = sqi + SQ[j+1] - 2.f * acc[mt][nt][half*2 + 1];
                            d2 = fmaxf(d2, EPSF);
                            d1 = d2 * rsqrtf(d2);
                        }
                        *(__half2*)(D + (long long)i*CC + j) = __floats2half2_rn(d0, d1);
                        lsum += d0 + d1;
                    }
                }
            }
        }
    }

    red[tid] = lsum;
    __syncthreads();
    #pragma unroll
    for (int s2 = 128; s2; s2 >>= 1) {
        if (tid < s2) red[tid] += red[tid + s2];
        __syncthreads();
    }
    if (tid == 0) {
        float w = diag ? 1.f : 2.f;
        atomicAdd(SM, red[0] * w);
    }
}

// ==================== kernel 3: Huber sum (64-tiles, fp16 D) ==============
__global__ void k_huber(float* __restrict__ out) {
    int n   = blockIdx.x;
    int tid = threadIdx.x;
    int P = g_npos[n];
    if (P <= 1) return;

    int tlin = blockIdx.y, bi = 0, rem = NT;
    while (tlin >= rem) { tlin -= rem; bi++; rem--; }
    int bj = bi + tlin;
    int i0 = bi * 64, j0 = bj * 64;
    if (i0 >= P || j0 >= P) return;

    float cnt = (float)P * (float)(P - 1);
    float ims = cnt / g_sum_s[n];
    float imt = cnt / g_sum_t[n];

    const __half* Ds = g_Ds + (long long)n*CC*CC;
    const __half* Dt = g_Dt + (long long)n*CC*CC;

    float lsum = 0.f;
    #pragma unroll
    for (int q = 0; q < 2; q++) {
        int f = tid + 256*q;          // 0..511 groups of 8 halves
        int i = i0 + (f >> 3);
        int j = j0 + (f & 7) * 8;
        if (i < P) {
            uint4 su = *(const uint4*)(Ds + (long long)i*CC + j);
            uint4 tu = *(const uint4*)(Dt + (long long)i*CC + j);
            const __half2* sh = (const __half2*)&su;
            const __half2* th = (const __half2*)&tu;
            #pragma unroll
            for (int p = 0; p < 4; p++) {
                float2 sf = __half22float2(sh[p]);
                float2 tf = __half22float2(th[p]);
                int jj = j + 2*p;
                if (jj < P) {
                    float diff = sf.x*ims - tf.x*imt;
                    float ad = fabsf(diff);
                    lsum += (ad < 1.f) ? 0.5f*diff*diff : ad - 0.5f;
                }
                if (jj + 1 < P) {
                    float diff = sf.y*ims - tf.y*imt;
                    float ad = fabsf(diff);
                    lsum += (ad < 1.f) ? 0.5f*diff*diff : ad - 0.5f;
                }
            }
        }
    }

    __shared__ float red[256];
    red[tid] = lsum;
    __syncthreads();
    #pragma unroll
    for (int s2 = 128; s2; s2 >>= 1) {
        if (tid < s2) red[tid] += red[tid + s2];
        __syncthreads();
    }
    if (tid == 0) {
        float w = (bi == bj) ? 1.f : 2.f;
        atomicAdd(out, red[0] * w / (float)P);
    }
}

// ============================== launcher =================================
extern "C" void kernel_launch(void* const* d_in, const int* in_sizes, int n_in,
                              void* d_out, int out_size) {
    const float* s    = (const float*)d_in[0];
    const float* t    = (const float*)d_in[1];
    const int*   targ = (const int*)d_in[2];
    float* out = (float*)d_out;

    k_index<<<NB, 512>>>(targ, out);
    dim3 g1(NB, 16);
    k_norm<<<g1, 256>>>(s, t);
    dim3 g2(NPAIR2, 2, NB);
    k_dist<<<g2, 256>>>(s, t);
    dim3 g3(NB, NPAIR);
    k_huber<<<g3, 256>>>(out);
}

// round 17
// speedup vs baseline: 1.1491x; 1.0988x over previous
#include <cuda_runtime.h>
#include <cuda_bf16.h>
#include <cuda_fp16.h>
#include <cstdint>

typedef unsigned int u32;

#define NB 64
#define CC 512
#define LL 256
#define EPSF 1e-12f
#define NT 8                    // 64-wide tiles for huber
#define NPAIR (NT*(NT+1)/2)     // 36
#define NT2 4                   // 128-wide tiles for dist
#define NPAIR2 (NT2*(NT2+1)/2)  // 10
#define SW 40                   // smem bf16 row stride (conflict-free ldmatrix)

// -------- scratch (static device globals: allocation-free rule) ----------
__device__ float  g_sq_s[NB*CC];
__device__ float  g_sq_t[NB*CC];
__device__ int    g_idx[NB*CC];
__device__ int    g_npos[NB];
__device__ float  g_sum_s[NB];
__device__ float  g_sum_t[NB];
__device__ __half g_Ds[NB*CC*CC];    // fp16 distance matrices (upper tiles)
__device__ __half g_Dt[NB*CC*CC];

// =================== kernel 0: index lists + init (tiny) ==================
__global__ void k_index(const int* __restrict__ targ, float* __restrict__ out) {
    int n    = blockIdx.x;
    int tid  = threadIdx.x;           // 512
    int lane = tid & 31;
    int wid  = tid >> 5;
    __shared__ int sh_wsum[16];

    int m = (targ[n*CC + tid] != 0);
    unsigned bal = __ballot_sync(0xffffffffu, m);
    int wpre = __popc(bal & ((1u << lane) - 1u));
    if (lane == 0) sh_wsum[wid] = __popc(bal);
    __syncthreads();
    if (tid == 0) {
        int acc = 0;
        #pragma unroll
        for (int w = 0; w < 16; w++) { int v = sh_wsum[w]; sh_wsum[w] = acc; acc += v; }
        g_npos[n]  = acc;
        g_sum_s[n] = 0.f;
        g_sum_t[n] = 0.f;
        if (n == 0) out[0] = 0.f;
    }
    __syncthreads();
    if (m) g_idx[n*CC + sh_wsum[wid] + wpre] = tid;
}

// ============ kernel 1: row norms via gather (no copy) ====================
__global__ void k_norm(const float* __restrict__ s, const float* __restrict__ t) {
    int n    = blockIdx.x;
    int P    = g_npos[n];
    int tid  = threadIdx.x;
    int lane = tid & 31;
    int wid  = tid >> 5;
    int gw   = blockIdx.y * 8 + wid;

    const float* sb = s + (long long)n*CC*LL;
    const float* tb = t + (long long)n*CC*LL;

    for (int r = gw; r < P; r += 128) {
        int src = g_idx[n*CC + r];
        const float4* rs = (const float4*)(sb + src*LL);
        const float4* rt = (const float4*)(tb + src*LL);
        float a = 0.f, b = 0.f;
        #pragma unroll
        for (int c = 0; c < 2; c++) {
            int e = lane + c*32;
            float4 v = rs[e];
            a += v.x*v.x + v.y*v.y + v.z*v.z + v.w*v.w;
            float4 w = rt[e];
            b += w.x*w.x + w.y*w.y + w.z*w.z + w.w*w.w;
        }
        #pragma unroll
        for (int off = 16; off; off >>= 1) {
            a += __shfl_down_sync(0xffffffffu, a, off);
            b += __shfl_down_sync(0xffffffffu, b, off);
        }
        if (lane == 0) { g_sq_s[n*CC + r] = a; g_sq_t[n*CC + r] = b; }
    }
}

// ----------------------- helpers -----------------------------------------
__device__ __forceinline__ void ldsm_x4(u32 (&r)[4], u32 addr) {
    asm volatile("ldmatrix.sync.aligned.m8n8.x4.shared.b16 {%0,%1,%2,%3}, [%4];"
        : "=r"(r[0]), "=r"(r[1]), "=r"(r[2]), "=r"(r[3]) : "r"(addr));
}

__device__ __forceinline__ void mma16816(float (&c)[4], const u32 (&a)[4],
                                         u32 b0, u32 b1) {
    asm volatile(
        "mma.sync.aligned.m16n8k16.row.col.f32.bf16.bf16.f32 "
        "{%0,%1,%2,%3},{%4,%5,%6,%7},{%8,%9},{%0,%1,%2,%3};"
        : "+f"(c[0]), "+f"(c[1]), "+f"(c[2]), "+f"(c[3])
        : "r"(a[0]), "r"(a[1]), "r"(a[2]), "r"(a[3]), "r"(b0), "r"(b1));
}

// load 16 floats (or zeros), split into hi/lo bf16, store 2x uint4 each
__device__ __forceinline__ void split16(const float* __restrict__ p, bool valid,
                                        __nv_bfloat16* hdst, __nv_bfloat16* ldst) {
    float v[16];
    if (valid) {
        #pragma unroll
        for (int q = 0; q < 4; q++) {
            float4 f = ((const float4*)p)[q];
            v[4*q+0] = f.x; v[4*q+1] = f.y; v[4*q+2] = f.z; v[4*q+3] = f.w;
        }
    } else {
        #pragma unroll
        for (int q = 0; q < 16; q++) v[q] = 0.f;
    }
    u32 hw[8], lw[8];
    #pragma unroll
    for (int q = 0; q < 8; q++) {
        float x0 = v[2*q], x1 = v[2*q+1];
        __nv_bfloat16 h0 = __float2bfloat16(x0);
        __nv_bfloat16 h1 = __float2bfloat16(x1);
        float r0 = x0 - __bfloat162float(h0);
        float r1 = x1 - __bfloat162float(h1);
        __nv_bfloat162 hp = __halves2bfloat162(h0, h1);
        __nv_bfloat162 lp = __halves2bfloat162(__float2bfloat16(r0), __float2bfloat16(r1));
        hw[q] = *(u32*)&hp;
        lw[q] = *(u32*)&lp;
    }
    ((uint4*)hdst)[0] = make_uint4(hw[0], hw[1], hw[2], hw[3]);
    ((uint4*)hdst)[1] = make_uint4(hw[4], hw[5], hw[6], hw[7]);
    ((uint4*)ldst)[0] = make_uint4(lw[0], lw[1], lw[2], lw[3]);
    ((uint4*)ldst)[1] = make_uint4(lw[4], lw[5], lw[6], lw[7]);
}

// ============ kernel 2: Gram -> distances via bf16-split HMMA =============
// 256 thr, 128x128 tile, warps 4(m)x2(n) each 32x64, K-chunk 32.
// dot = Ah*Bh + Ah*Bl + Al*Bh  (2-term bf16 split, ~fp32 precision)
// R11 loop structure (known-good); only the D store is fp16 now.
__global__ void __launch_bounds__(256, 2) k_dist(const float* __restrict__ s,
                                                 const float* __restrict__ t) {
    int n     = blockIdx.z;
    int which = blockIdx.y;

    const float* E  = (which ? t : s) + (long long)n*CC*LL;
    const float* SQ = which ? (g_sq_t + n*CC)               : (g_sq_s + n*CC);
    __half*      D  = which ? (g_Dt   + (long long)n*CC*CC) : (g_Ds   + (long long)n*CC*CC);
    float*       SM = which ? (g_sum_t + n)                 : (g_sum_s + n);

    int P = g_npos[n];

    int tlin = blockIdx.x, bi = 0, rem = NT2;
    while (tlin >= rem) { tlin -= rem; bi++; rem--; }
    int bj = bi + tlin;
    int i0 = bi * 128, j0 = bj * 128;
    if (i0 >= P || j0 >= P) return;
    bool diag = (bi == bj);

    __shared__ __align__(16) __nv_bfloat16 Ah[128*SW];
    __shared__ __align__(16) __nv_bfloat16 Al[128*SW];
    __shared__ __align__(16) __nv_bfloat16 Bhs[128*SW];
    __shared__ __align__(16) __nv_bfloat16 Bls[128*SW];
    __shared__ int sIA[128];
    __shared__ int sIB[128];
    __shared__ float red[256];

    int tid  = threadIdx.x;
    int lane = tid & 31;
    int wid  = tid >> 5;
    int wm   = wid & 3;
    int wn   = wid >> 2;              // warp tile origin: (wm*32, wn*64)

    if (tid < 128) {
        int gi = i0 + tid;
        sIA[tid] = (gi < P) ? g_idx[n*CC + gi] : -1;
        int gj = j0 + tid;
        sIB[tid] = (gj < P) ? g_idx[n*CC + gj] : -1;
    }

    u32 ah = (u32)__cvta_generic_to_shared(Ah);
    u32 al = (u32)__cvta_generic_to_shared(Al);
    u32 bh = diag ? ah : (u32)__cvta_generic_to_shared(Bhs);
    u32 bl = diag ? al : (u32)__cvta_generic_to_shared(Bls);

    float acc[2][8][4];
    #pragma unroll
    for (int mt = 0; mt < 2; mt++) {
        #pragma unroll
        for (int nt = 0; nt < 8; nt++) {
            #pragma unroll
            for (int e = 0; e < 4; e++) acc[mt][nt][e] = 0.f;
        }
    }

    int lrow = tid >> 1;              // loader row 0..127
    int kb   = (tid & 1) * 16;        // loader k-offset 0/16

    u32 a_r = (lane & 7) + ((lane >> 3) & 1) * 8;
    u32 a_k = (lane >> 4) * 8;
    u32 b_r = (lane & 7) + (lane >> 4) * 8;
    u32 b_k = ((lane >> 3) & 1) * 8;

    __syncthreads();
    int srcA = sIA[lrow];
    int srcB = sIB[lrow];

    for (int k0 = 0; k0 < LL; k0 += 32) {
        split16(E + srcA*LL + k0 + kb, srcA >= 0,
                &Ah[lrow*SW + kb], &Al[lrow*SW + kb]);
        if (!diag) {
            split16(E + srcB*LL + k0 + kb, srcB >= 0,
                    &Bhs[lrow*SW + kb], &Bls[lrow*SW + kb]);
        }
        __syncthreads();

        #pragma unroll
        for (int ks = 0; ks < 32; ks += 16) {
            #pragma unroll
            for (int pass = 0; pass < 3; pass++) {
                u32 abase = (pass < 2)  ? ah : al;
                u32 bbase = (pass == 1) ? bl : bh;
                u32 afrag[2][4];
                #pragma unroll
                for (int mt = 0; mt < 2; mt++) {
                    u32 arow = wm*32 + mt*16 + a_r;
                    ldsm_x4(afrag[mt], abase + (arow*SW + ks + a_k)*2);
                }
                #pragma unroll
                for (int ng = 0; ng < 4; ng++) {
                    u32 brow = wn*64 + ng*16 + b_r;
                    u32 bfrag[4];
                    ldsm_x4(bfrag, bbase + (brow*SW + ks + b_k)*2);
                    #pragma unroll
                    for (int mt = 0; mt < 2; mt++) {
                        mma16816(acc[mt][ng*2+0], afrag[mt], bfrag[0], bfrag[1]);
                        mma16816(acc[mt][ng*2+1], afrag[mt], bfrag[2], bfrag[3]);
                    }
                }
            }
        }
        __syncthreads();
    }

    // ---- epilogue: distances (fp16 pairs), partial sum ----
    float lsum = 0.f;
    #pragma unroll
    for (int mt = 0; mt < 2; mt++) {
        #pragma unroll
        for (int half = 0; half < 2; half++) {
            int i = i0 + wm*32 + mt*16 + (lane >> 2) + half*8;
            if (i < P) {
                float sqi = SQ[i];
                #pragma unroll
                for (int nt = 0; nt < 8; nt++) {
                    int j = j0 + wn*64 + nt*8 + (lane & 3)*2;
                    if (j < P) {
                        float d0 = 0.f, d1 = 0.f;
                        if (i != j) {
                            float d2 = sqi + SQ[j] - 2.f * acc[mt][nt][half*2 + 0];
                            d2 = fmaxf(d2, EPSF);
                            d0 = d2 * rsqrtf(d2);
                        }
                        if (j + 1 < P && i != j + 1) {
                            float d2 = sqi + SQ[j+1] - 2.f * acc[mt][nt][half*2 + 1];
                            d2 = fmaxf(d2, EPSF);
                            d1 = d2 * rsqrtf(d2);
                        }
                        *(__half2*)(D + (long long)i*CC + j) = __floats2half2_rn(d0, d1);
                        lsum += d0 + d1;
                    }
                }
            }
        }
    }

    red[tid] = lsum;
    __syncthreads();
    #pragma unroll
    for (int s2 = 128; s2; s2 >>= 1) {
        if (tid < s2) red[tid] += red[tid + s2];
        __syncthreads();
    }
    if (tid == 0) {
        float w = diag ? 1.f : 2.f;
        atomicAdd(SM, red[0] * w);
    }
}

// ==================== kernel 3: Huber sum (64-tiles, fp16 D) ==============
__global__ void k_huber(float* __restrict__ out) {
    int n   = blockIdx.x;
    int tid = threadIdx.x;
    int P = g_npos[n];
    if (P <= 1) return;

    int tlin = blockIdx.y, bi = 0, rem = NT;
    while (tlin >= rem) { tlin -= rem; bi++; rem--; }
    int bj = bi + tlin;
    int i0 = bi * 64, j0 = bj * 64;
    if (i0 >= P || j0 >= P) return;

    float cnt = (float)P * (float)(P - 1);
    float ims = cnt / g_sum_s[n];
    float imt = cnt / g_sum_t[n];

    const __half* Ds = g_Ds + (long long)n*CC*CC;
    const __half* Dt = g_Dt + (long long)n*CC*CC;

    float lsum = 0.f;
    #pragma unroll
    for (int q = 0; q < 2; q++) {
        int f = tid + 256*q;          // 0..511 groups of 8 halves
        int i = i0 + (f >> 3);
        int j = j0 + (f & 7) * 8;
        if (i < P) {
            uint4 su = *(const uint4*)(Ds + (long long)i*CC + j);
            uint4 tu = *(const uint4*)(Dt + (long long)i*CC + j);
            const __half2* sh = (const __half2*)&su;
            const __half2* th = (const __half2*)&tu;
            #pragma unroll
            for (int p = 0; p < 4; p++) {
                float2 sf = __half22float2(sh[p]);
                float2 tf = __half22float2(th[p]);
                int jj = j + 2*p;
                if (jj < P) {
                    float diff = sf.x*ims - tf.x*imt;
                    float ad = fabsf(diff);
                    lsum += (ad < 1.f) ? 0.5f*diff*diff : ad - 0.5f;
                }
                if (jj + 1 < P) {
                    float diff = sf.y*ims - tf.y*imt;
                    float ad = fabsf(diff);
                    lsum += (ad < 1.f) ? 0.5f*diff*diff : ad - 0.5f;
                }
            }
        }
    }

    __shared__ float red[256];
    red[tid] = lsum;
    __syncthreads();
    #pragma unroll
    for (int s2 = 128; s2; s2 >>= 1) {
        if (tid < s2) red[tid] += red[tid + s2];
        __syncthreads();
    }
    if (tid == 0) {
        float w = (bi == bj) ? 1.f : 2.f;
        atomicAdd(out, red[0] * w / (float)P);
    }
}

// ============================== launcher =================================
extern "C" void kernel_launch(void* const* d_in, const int* in_sizes, int n_in,
                              void* d_out, int out_size) {
    const float* s    = (const float*)d_in[0];
    const float* t    = (const float*)d_in[1];
    const int*   targ = (const int*)d_in[2];
    float* out = (float*)d_out;

    k_index<<<NB, 512>>>(targ, out);
    dim3 g1(NB, 16);
    k_norm<<<g1, 256>>>(s, t);
    dim3 g2(NPAIR2, 2, NB);
    k_dist<<<g2, 256>>>(s, t);
    dim3 g3(NB, NPAIR);
    k_huber<<<g3, 256>>>(out);
}